// round 9
// baseline (speedup 1.0000x reference)
#include <cuda_runtime.h>
#include <cuda_fp16.h>
#include <cstdint>

// ---------------------------------------------------------------------------
// out = sum_p w_p * kron8(blocks[idx[p]])  -> 256x256
// kp_p = A_p (codons 0-3) (x) B_p (codons 4-7); G[a,b] = sum_p (w_p A_p[a]) B_p[b]
// out[(iH*16+iL)*256+(jH*16+jL)] = G[iH*16+jH, iL*16+jL]
// Kron of ternary blocks is ternary => A = w*T. Split w = w_hi + w_lo (fp16):
// A_hi, A_lo, B are EXACT fp16. G = A_hi^T B + A_lo^T B via mma.sync f16->f32.
// R6: operand tiles generated in smem inside the GEMM (no gmem round-trip).
// R9: SINGLE kernel. 148 CTAs = one resident wave -> software grid barrier
//     (monotonic ticket, replay-safe), then in-kernel L2-hot split-K reduce.
// ---------------------------------------------------------------------------

#define POP      4096
#define SPLITK   37
#define KCHUNK   112                 // 37*112 = 4144 (padded K; pad genomes -> 0)
#define LDT      136                 // padded smem tile row (halfs)
#define RSLICES  40                  // reduce reads 40 slices (37..39 stay zero)
#define NCTAS    148

__device__ float g_part[RSLICES * 256 * 256];   // slices 37-39 never written
__device__ unsigned g_ctr;                      // monotonic barrier ticket

// ---------------- warp-MMA helpers (sm_80+ PTX, valid at compute_103 base) --
__device__ __forceinline__ unsigned smem_u32(const void* p) {
    unsigned a;
    asm("{ .reg .u64 t; cvta.to.shared.u64 t, %1; cvt.u32.u64 %0, t; }" : "=r"(a) : "l"(p));
    return a;
}
__device__ __forceinline__ void ldsm_x4_t(uint32_t* r, unsigned a) {
    asm volatile("ldmatrix.sync.aligned.m8n8.x4.trans.shared.b16 {%0,%1,%2,%3}, [%4];"
                 : "=r"(r[0]), "=r"(r[1]), "=r"(r[2]), "=r"(r[3]) : "r"(a));
}
__device__ __forceinline__ void ldsm_x2_t(uint32_t* r, unsigned a) {
    asm volatile("ldmatrix.sync.aligned.m8n8.x2.trans.shared.b16 {%0,%1}, [%2];"
                 : "=r"(r[0]), "=r"(r[1]) : "r"(a));
}
__device__ __forceinline__ void mma16816(float* d, const uint32_t* a, const uint32_t* b) {
    asm volatile("mma.sync.aligned.m16n8k16.row.col.f32.f16.f16.f32 "
                 "{%0,%1,%2,%3}, {%4,%5,%6,%7}, {%8,%9}, {%0,%1,%2,%3};"
                 : "+f"(d[0]), "+f"(d[1]), "+f"(d[2]), "+f"(d[3])
                 : "r"(a[0]), "r"(a[1]), "r"(a[2]), "r"(a[3]), "r"(b[0]), "r"(b[1]));
}

// ---------------------------------------------------------------------------
// Fused kernel: grid (2 mb, 2 nb, 37 z) = 148 CTAs, 256 threads.
// Phase 1: generate As/Al (A hi/lo) and Bs tiles in smem.
// Phase 2: 128x128 fp32 accum via mma.sync, write split-K partial.
// Phase 3: grid barrier; per-CTA slice of the cross-z reduce (L2-hot).
// ---------------------------------------------------------------------------
__global__ void __launch_bounds__(256, 1) fused_kernel(
        const float* __restrict__ w,
        const int*   __restrict__ idxg,
        const float* __restrict__ bbg,
        float*       __restrict__ out) {
    extern __shared__ __half smem[];
    __half* As = smem;                       // [KCHUNK][LDT]
    __half* Al = smem + KCHUNK * LDT;
    __half* Bs = smem + 2 * KCHUNK * LDT;
    __shared__ float bb[144];
    __shared__ int   sidx[KCHUNK * 8];
    __shared__ float sw[KCHUNK];

    const int tid = threadIdx.x, lane = tid & 31, wid = tid >> 5;
    const int mb = blockIdx.x, nb = blockIdx.y, z = blockIdx.z;
    const int gbase = z * KCHUNK;

    // ---- Stage constants ----
    if (tid < 144) bb[tid] = bbg[tid];
    #pragma unroll
    for (int i = tid; i < KCHUNK * 8; i += 256) {
        const int g = gbase + (i >> 3);
        sidx[i] = (g < POP) ? __ldg(&idxg[g * 8 + (i & 7)]) : 0;
    }
    if (tid < KCHUNK) {
        const int g = gbase + tid;
        sw[tid] = (g < POP) ? __ldg(&w[g]) : 0.f;   // w=0 -> zero A rows (pad)
    }
    __syncthreads();

    // ---- Phase 1a: A side (hi/lo). (g,x) tasks, x = mb*8 + xi ----
    for (int i = tid; i < KCHUNK * 8; i += 256) {
        const int gl = i >> 3, xi = i & 7;
        const int* ip = &sidx[gl * 8];
        const float u = bb[ip[0] * 4 + (mb & 1) * 2 + ((xi >> 1) & 1)]
                      * bb[ip[1] * 4 + ((xi >> 2) & 1) * 2 + (xi & 1)];
        float V[16];
        #pragma unroll
        for (int p = 0; p < 2; p++)
          #pragma unroll
          for (int q = 0; q < 2; q++)
            #pragma unroll
            for (int r = 0; r < 2; r++)
              #pragma unroll
              for (int s = 0; s < 2; s++)
                  V[(p*2+q)*4 + (r*2+s)] = bb[ip[2]*4 + p*2 + r] * bb[ip[3]*4 + q*2 + s];

        const float wf  = sw[gl];
        const float whf = __half2float(__float2half_rn(wf));
        const float wlf = __half2float(__float2half_rn(wf - whf));
        const __half2 ph = __float2half2_rn(whf * u);   // exact: {0, +/-w_hi}
        const __half2 pl = __float2half2_rn(wlf * u);

        const int colbase = (((xi >> 2) & 1) << 6) | ((xi & 3) << 2);
        #pragma unroll
        for (int qq = 0; qq < 4; qq++) {
            __half2 v0 = __floats2half2_rn(V[4*qq],   V[4*qq+1]);
            __half2 v1 = __floats2half2_rn(V[4*qq+2], V[4*qq+3]);
            __half2 h0 = __hmul2(ph, v0), h1 = __hmul2(ph, v1);
            __half2 l0 = __hmul2(pl, v0), l1 = __hmul2(pl, v1);
            const int col = colbase | (qq << 4);
            uint2 uh; uh.x = *(unsigned*)&h0; uh.y = *(unsigned*)&h1;
            uint2 ul; ul.x = *(unsigned*)&l0; ul.y = *(unsigned*)&l1;
            *(uint2*)&As[gl * LDT + col] = uh;
            *(uint2*)&Al[gl * LDT + col] = ul;
        }
    }

    // ---- Phase 1b: B side. (g,x) tasks, x = nb*8 + xi ----
    for (int i = tid; i < KCHUNK * 8; i += 256) {
        const int gl = i >> 3, xi = i & 7;
        const int* ip = &sidx[gl * 8];
        float u = bb[ip[4] * 4 + (nb & 1) * 2 + ((xi >> 1) & 1)]
                * bb[ip[5] * 4 + ((xi >> 2) & 1) * 2 + (xi & 1)];
        if (gbase + gl >= POP) u = 0.f;                // zero pad rows
        float V[16];
        #pragma unroll
        for (int p = 0; p < 2; p++)
          #pragma unroll
          for (int q = 0; q < 2; q++)
            #pragma unroll
            for (int r = 0; r < 2; r++)
              #pragma unroll
              for (int s = 0; s < 2; s++)
                  V[(p*2+q)*4 + (r*2+s)] = bb[ip[6]*4 + p*2 + r] * bb[ip[7]*4 + q*2 + s];

        const __half2 uh2 = __float2half2_rn(u);
        const int colbase = (((xi >> 2) & 1) << 6) | ((xi & 3) << 2);
        #pragma unroll
        for (int qq = 0; qq < 4; qq++) {
            __half2 v0 = __floats2half2_rn(V[4*qq],   V[4*qq+1]);
            __half2 v1 = __floats2half2_rn(V[4*qq+2], V[4*qq+3]);
            __half2 h0 = __hmul2(uh2, v0), h1 = __hmul2(uh2, v1);
            const int col = colbase | (qq << 4);
            uint2 uv; uv.x = *(unsigned*)&h0; uv.y = *(unsigned*)&h1;
            *(uint2*)&Bs[gl * LDT + col] = uv;
        }
    }
    __syncthreads();

    // ---- Phase 2: HMMA mainloop ----
    const int wm = wid & 1;                // m-half: 64 rows
    const int wn = wid >> 1;               // n-quarter: 32 cols
    const int arow = (lane & 7) + ((lane >> 4) << 3);
    const int acol = wm * 64 + ((lane >> 3) & 1) * 8;
    const int bl = lane & 15;
    const int brow = (bl & 7) + ((bl >> 3) << 3);

    const unsigned aHi = smem_u32(&As[arow * LDT + acol]);
    const unsigned aLo = smem_u32(&Al[arow * LDT + acol]);
    const unsigned bBa = smem_u32(&Bs[brow * LDT + wn * 32]);

    float acc[4][4][4];
    #pragma unroll
    for (int i = 0; i < 4; i++)
        #pragma unroll
        for (int j = 0; j < 4; j++)
            #pragma unroll
            for (int q = 0; q < 4; q++) acc[i][j][q] = 0.f;

    #pragma unroll
    for (int ks = 0; ks < KCHUNK / 16; ks++) {
        const unsigned ko = (unsigned)(ks * 16 * LDT * 2);
        uint32_t bf[4][2];
        #pragma unroll
        for (int nt = 0; nt < 4; nt++) ldsm_x2_t(bf[nt], bBa + ko + nt * 8 * 2);
        uint32_t ah[4][4], al[4][4];
        #pragma unroll
        for (int mt = 0; mt < 4; mt++) {
            ldsm_x4_t(ah[mt], aHi + ko + mt * 16 * 2);
            ldsm_x4_t(al[mt], aLo + ko + mt * 16 * 2);
        }
        #pragma unroll
        for (int mt = 0; mt < 4; mt++)
            #pragma unroll
            for (int nt = 0; nt < 4; nt++) {
                mma16816(acc[mt][nt], ah[mt], bf[nt]);
                mma16816(acc[mt][nt], al[mt], bf[nt]);
            }
    }

    // ---- Epilogue: write split-K partial ----
    float* part = g_part + z * 65536;
    const int r0 = mb * 128 + wm * 64;
    const int c0 = nb * 128 + wn * 32;
    #pragma unroll
    for (int mt = 0; mt < 4; mt++)
        #pragma unroll
        for (int nt = 0; nt < 4; nt++) {
            const int a = r0 + mt * 16 + (lane >> 2);
            const int b = c0 + nt * 8 + (lane & 3) * 2;
            *(float2*)&part[a * 256 + b]       = make_float2(acc[mt][nt][0], acc[mt][nt][1]);
            *(float2*)&part[(a + 8) * 256 + b] = make_float2(acc[mt][nt][2], acc[mt][nt][3]);
        }

    // ---- Phase 3: grid barrier (148 CTAs = 1 resident wave; ticket is
    // monotonic so no reset needed across graph replays) ----
    __threadfence();
    __syncthreads();
    if (tid == 0) {
        const unsigned old = atomicAdd(&g_ctr, 1u);
        const unsigned target = (old / NCTAS + 1u) * NCTAS;
        unsigned cur;
        do {
            asm volatile("ld.acquire.gpu.u32 %0, [%1];" : "=r"(cur) : "l"(&g_ctr));
        } while (cur < target);
        __threadfence();
    }
    __syncthreads();

    // ---- Reduce: this CTA handles 111 of 16384 output-float4s.
    // 2 threads per output, 20 slices each (2 x 10-deep batches), shfl combine.
    const int cta = (z << 2) | (mb << 1) | nb;      // 0..147
    if (tid < 224) {
        const int ol   = tid >> 1;                  // 0..111
        const int half = tid & 1;
        const int o    = cta * 111 + ol;
        const bool valid = (ol < 111) && (o < 16384);
        const int oc = valid ? o : 0;
        const float4* src = (const float4*)g_part + oc + (size_t)(half * 20) * 16384;

        float4 s = make_float4(0.f, 0.f, 0.f, 0.f);
        #pragma unroll
        for (int bch = 0; bch < 2; bch++) {
            float4 v[10];
            #pragma unroll
            for (int k = 0; k < 10; k++)
                v[k] = __ldcg(&src[(size_t)(bch * 10 + k) * 16384]);
            #pragma unroll
            for (int k = 0; k < 10; k++) {
                s.x += v[k].x; s.y += v[k].y; s.z += v[k].z; s.w += v[k].w;
            }
        }
        s.x += __shfl_xor_sync(0xffffffffu, s.x, 1);
        s.y += __shfl_xor_sync(0xffffffffu, s.y, 1);
        s.z += __shfl_xor_sync(0xffffffffu, s.z, 1);
        s.w += __shfl_xor_sync(0xffffffffu, s.w, 1);

        if (half == 0 && valid) {
            const int tt = o * 4;
            const int a = tt >> 8, b = tt & 255;
            const int iH = a >> 4, jH = a & 15;
            const int iL = b >> 4, jL = b & 15;     // jL multiple of 4
            *(float4*)(out + (iH * 16 + iL) * 256 + jH * 16 + jL) = s;
        }
    }
}

extern "C" void kernel_launch(void* const* d_in, const int* in_sizes, int n_in,
                              void* d_out, int out_size) {
    const float* w   = (const float*)d_in[0];
    const int*   idx = (const int*)  d_in[1];
    const float* bb  = (const float*)d_in[2];

    const int smem_bytes = 3 * KCHUNK * LDT * (int)sizeof(__half);  // 91392
    cudaFuncSetAttribute(fused_kernel, cudaFuncAttributeMaxDynamicSharedMemorySize, smem_bytes);

    fused_kernel<<<dim3(2, 2, SPLITK), 256, smem_bytes>>>(w, idx, bb, (float*)d_out);
}

// round 11
// speedup vs baseline: 1.1376x; 1.1376x over previous
#include <cuda_runtime.h>
#include <cuda_fp16.h>
#include <cstdint>

// ---------------------------------------------------------------------------
// out = sum_p w_p * kron8(blocks[idx[p]])  -> 256x256
// G[a,b] = sum_p (w_p A_p[a]) B_p[b];  out[(iH16+iL),(jH16+jL)] = G[iH16+jH, iL16+jL]
// A = w*ternary -> split w = w_hi + w_lo (fp16): A_hi, A_lo, B exact fp16.
// G = A_hi^T B + A_lo^T B via mma.sync f16->f32, tiles generated in smem.
// R10: 64x128 tiles, grid (4,2,18); SPLITK 18 halves partial traffic;
//      per-genome V-table pre-pass.  R11: fix vt[] size (2 uint4 per entry).
// ---------------------------------------------------------------------------

#define POP      4096
#define SPLITK   18
#define KCHUNK   240                 // 18*240 = 4320 (pad genomes -> 0)
#define KSTEPS   15                  // 240/16
#define LDTA     72                  // A tile row stride (halfs), 64 + pad
#define LDTB     136                 // B tile row stride (halfs), 128 + pad

__device__ float g_part[SPLITK * 256 * 256];   // 4.7 MB split-K partials

// ---------------- warp-MMA helpers (sm_80+ PTX, valid at compute_103) ------
__device__ __forceinline__ unsigned smem_u32(const void* p) {
    unsigned a;
    asm("{ .reg .u64 t; cvta.to.shared.u64 t, %1; cvt.u32.u64 %0, t; }" : "=r"(a) : "l"(p));
    return a;
}
__device__ __forceinline__ void ldsm_x4_t(uint32_t* r, unsigned a) {
    asm volatile("ldmatrix.sync.aligned.m8n8.x4.trans.shared.b16 {%0,%1,%2,%3}, [%4];"
                 : "=r"(r[0]), "=r"(r[1]), "=r"(r[2]), "=r"(r[3]) : "r"(a));
}
__device__ __forceinline__ void ldsm_x2_t(uint32_t* r, unsigned a) {
    asm volatile("ldmatrix.sync.aligned.m8n8.x2.trans.shared.b16 {%0,%1}, [%2];"
                 : "=r"(r[0]), "=r"(r[1]) : "r"(a));
}
__device__ __forceinline__ void mma16816(float* d, const uint32_t* a, const uint32_t* b) {
    asm volatile("mma.sync.aligned.m16n8k16.row.col.f32.f16.f16.f32 "
                 "{%0,%1,%2,%3}, {%4,%5,%6,%7}, {%8,%9}, {%0,%1,%2,%3};"
                 : "+f"(d[0]), "+f"(d[1]), "+f"(d[2]), "+f"(d[3])
                 : "r"(a[0]), "r"(a[1]), "r"(a[2]), "r"(a[3]), "r"(b[0]), "r"(b[1]));
}

// ---------------------------------------------------------------------------
// Fused kernel: grid (4 mb, 2 nb, 18 z) = 144 CTAs, 256 threads.
// A tile 64 a-cols (a bits [7:6] = mb), B tile 128 b-cols (b bit 7 = nb).
// ---------------------------------------------------------------------------
__global__ void __launch_bounds__(256, 1) fused_kernel(
        const float* __restrict__ w,
        const int*   __restrict__ idxg,
        const float* __restrict__ bbg) {
    extern __shared__ __half smem[];
    __half* As = smem;                               // [KCHUNK][LDTA]
    __half* Al = smem + KCHUNK * LDTA;
    __half* Bs = smem + 2 * KCHUNK * LDTA;           // [KCHUNK][LDTB]
    __shared__ float bb[144];
    __shared__ int   sidx[KCHUNK * 8];
    __shared__ float sw[KCHUNK];
    __shared__ uint4 vt[4 * KCHUNK];                 // V-tables: 2 uint4/entry!

    const int tid = threadIdx.x, lane = tid & 31, wid = tid >> 5;
    const int mb = blockIdx.x, nb = blockIdx.y, z = blockIdx.z;
    const int gbase = z * KCHUNK;

    // ---- Stage constants ----
    if (tid < 144) bb[tid] = bbg[tid];
    #pragma unroll
    for (int i = tid; i < KCHUNK * 8; i += 256) {
        const int g = gbase + (i >> 3);
        sidx[i] = (g < POP) ? __ldg(&idxg[g * 8 + (i & 7)]) : 0;
    }
    if (tid < KCHUNK) {
        const int g = gbase + tid;
        sw[tid] = (g < POP) ? __ldg(&w[g]) : 0.f;    // w=0 -> zero A rows (pad)
    }
    __syncthreads();

    // ---- Pre-pass: per-(genome, side) V-table (kron of codons 2,3 / 6,7) ----
    for (int i = tid; i < 2 * KCHUNK; i += 256) {
        const int gl = (i < KCHUNK) ? i : (i - KCHUNK);
        const int cb = (i < KCHUNK) ? 2 : 6;
        const int ia = sidx[gl * 8 + cb], ib = sidx[gl * 8 + cb + 1];
        __half2 Vh[8];
        #pragma unroll
        for (int p = 0; p < 2; p++)
          #pragma unroll
          for (int q = 0; q < 2; q++)
            #pragma unroll
            for (int r = 0; r < 2; r++) {
                const float va = bb[ia * 4 + p * 2 + r];
                Vh[((p*2+q)*4 + r*2) >> 1] =
                    __floats2half2_rn(va * bb[ib * 4 + q * 2],
                                      va * bb[ib * 4 + q * 2 + 1]);
            }
        uint4 u0, u1;
        u0.x = *(unsigned*)&Vh[0]; u0.y = *(unsigned*)&Vh[1];
        u0.z = *(unsigned*)&Vh[2]; u0.w = *(unsigned*)&Vh[3];
        u1.x = *(unsigned*)&Vh[4]; u1.y = *(unsigned*)&Vh[5];
        u1.z = *(unsigned*)&Vh[6]; u1.w = *(unsigned*)&Vh[7];
        vt[i * 2]     = u0;
        vt[i * 2 + 1] = u1;
    }
    __syncthreads();

    // ---- Build A hi/lo: tasks (gl, xi), xi 0..3; x = mb*4 + xi ----
    for (int i = tid; i < KCHUNK * 4; i += 256) {
        const int gl = i >> 2, xi = i & 3;
        const float u = bb[sidx[gl*8+0] * 4 + (mb >> 1) * 2 + (xi >> 1)]
                      * bb[sidx[gl*8+1] * 4 + (mb & 1) * 2 + (xi & 1)];
        const float wf  = sw[gl];
        const float whf = __half2float(__float2half_rn(wf));
        const float wlf = __half2float(__float2half_rn(wf - whf));
        const __half2 ph = __float2half2_rn(whf * u);   // exact {0, +/-w_hi}
        const __half2 pl = __float2half2_rn(wlf * u);

        const uint4 v0 = vt[gl * 2], v1 = vt[gl * 2 + 1];
        const unsigned vv[8] = {v0.x, v0.y, v0.z, v0.w, v1.x, v1.y, v1.z, v1.w};
        #pragma unroll
        for (int qq = 0; qq < 4; qq++) {
            const __half2 a0 = *(const __half2*)&vv[2*qq];
            const __half2 a1 = *(const __half2*)&vv[2*qq+1];
            __half2 h0 = __hmul2(ph, a0), h1 = __hmul2(ph, a1);
            __half2 l0 = __hmul2(pl, a0), l1 = __hmul2(pl, a1);
            const int col = (qq << 4) | (xi << 2);
            uint2 uh; uh.x = *(unsigned*)&h0; uh.y = *(unsigned*)&h1;
            uint2 ul; ul.x = *(unsigned*)&l0; ul.y = *(unsigned*)&l1;
            *(uint2*)&As[gl * LDTA + col] = uh;
            *(uint2*)&Al[gl * LDTA + col] = ul;
        }
    }

    // ---- Build B: tasks (gl, xi), xi 0..7; x = nb*8 + xi ----
    for (int i = tid; i < KCHUNK * 8; i += 256) {
        const int gl = i >> 3, xi = i & 7;
        float u = bb[sidx[gl*8+4] * 4 + nb * 2 + ((xi >> 1) & 1)]
                * bb[sidx[gl*8+5] * 4 + ((xi >> 2) & 1) * 2 + (xi & 1)];
        if (gbase + gl >= POP) u = 0.f;              // zero pad rows
        const __half2 uh2 = __float2half2_rn(u);

        const uint4 v0 = vt[(KCHUNK + gl) * 2], v1 = vt[(KCHUNK + gl) * 2 + 1];
        const unsigned vv[8] = {v0.x, v0.y, v0.z, v0.w, v1.x, v1.y, v1.z, v1.w};
        const int colbase = (((xi >> 2) & 1) << 6) | ((xi & 3) << 2);
        #pragma unroll
        for (int qq = 0; qq < 4; qq++) {
            const __half2 a0 = *(const __half2*)&vv[2*qq];
            const __half2 a1 = *(const __half2*)&vv[2*qq+1];
            __half2 h0 = __hmul2(uh2, a0), h1 = __hmul2(uh2, a1);
            const int col = colbase | (qq << 4);
            uint2 uv; uv.x = *(unsigned*)&h0; uv.y = *(unsigned*)&h1;
            *(uint2*)&Bs[gl * LDTB + col] = uv;
        }
    }
    __syncthreads();

    // ---- HMMA mainloop: 8 warps, 32x32 warp tiles (2 m-halves x 4 n-quarters)
    const int wm = wid & 1;
    const int wn = wid >> 1;
    const int arow = (lane & 7) + ((lane >> 4) << 3);
    const int acol = wm * 32 + ((lane >> 3) & 1) * 8;
    const int bl = lane & 15;
    const int brow = (bl & 7) + ((bl >> 3) << 3);

    const unsigned aHi = smem_u32(&As[arow * LDTA + acol]);
    const unsigned aLo = smem_u32(&Al[arow * LDTA + acol]);
    const unsigned bBa = smem_u32(&Bs[brow * LDTB + wn * 32]);

    float acc[2][4][4];
    #pragma unroll
    for (int i = 0; i < 2; i++)
        #pragma unroll
        for (int j = 0; j < 4; j++)
            #pragma unroll
            for (int q = 0; q < 4; q++) acc[i][j][q] = 0.f;

    #pragma unroll
    for (int ks = 0; ks < KSTEPS; ks++) {
        const unsigned koa = (unsigned)(ks * 16 * LDTA * 2);
        const unsigned kob = (unsigned)(ks * 16 * LDTB * 2);
        uint32_t bf[4][2];
        #pragma unroll
        for (int nt = 0; nt < 4; nt++) ldsm_x2_t(bf[nt], bBa + kob + nt * 16);
        uint32_t ah[2][4], al[2][4];
        #pragma unroll
        for (int mt = 0; mt < 2; mt++) {
            ldsm_x4_t(ah[mt], aHi + koa + mt * 32);
            ldsm_x4_t(al[mt], aLo + koa + mt * 32);
        }
        #pragma unroll
        for (int mt = 0; mt < 2; mt++)
            #pragma unroll
            for (int nt = 0; nt < 4; nt++) {
                mma16816(acc[mt][nt], ah[mt], bf[nt]);
                mma16816(acc[mt][nt], al[mt], bf[nt]);
            }
    }

    // ---- Epilogue: write 64x128 split-K partial ----
    float* part = g_part + z * 65536;
    const int r0 = mb * 64 + wm * 32;
    const int c0 = nb * 128 + wn * 32;
    #pragma unroll
    for (int mt = 0; mt < 2; mt++)
        #pragma unroll
        for (int nt = 0; nt < 4; nt++) {
            const int a = r0 + mt * 16 + (lane >> 2);
            const int b = c0 + nt * 8 + (lane & 3) * 2;
            *(float2*)&part[a * 256 + b]       = make_float2(acc[mt][nt][0], acc[mt][nt][1]);
            *(float2*)&part[(a + 8) * 256 + b] = make_float2(acc[mt][nt][2], acc[mt][nt][3]);
        }
}

// ---------------------------------------------------------------------------
// Reduce: 2 k-groups x 9 slices (const unroll, MLP=9), 32K threads,
// smem combine, Kronecker-permuted store.
// ---------------------------------------------------------------------------
__global__ void __launch_bounds__(256) reduce_kernel(float* __restrict__ out) {
    __shared__ float4 red[128];
    const int t = threadIdx.x;
    const int t4 = blockIdx.x * 128 + (t & 127);
    const int ks = t >> 7;                           // 0..1
    const float4* src = (const float4*)g_part + (size_t)ks * 9 * 16384 + t4;

    float4 v[9];
    #pragma unroll
    for (int k = 0; k < 9; k++) v[k] = src[(size_t)k * 16384];

    float4 s = v[0];
    #pragma unroll
    for (int k = 1; k < 9; k++) {
        s.x += v[k].x; s.y += v[k].y; s.z += v[k].z; s.w += v[k].w;
    }
    if (ks == 1) red[t & 127] = s;
    __syncthreads();
    if (ks == 0) {
        const float4 r = red[t];
        s.x += r.x; s.y += r.y; s.z += r.z; s.w += r.w;
        const int tt = t4 * 4;
        const int a = tt >> 8, b = tt & 255;
        const int iH = a >> 4, jH = a & 15;
        const int iL = b >> 4, jL = b & 15;          // jL multiple of 4
        *(float4*)(out + (iH * 16 + iL) * 256 + jH * 16 + jL) = s;
    }
}

extern "C" void kernel_launch(void* const* d_in, const int* in_sizes, int n_in,
                              void* d_out, int out_size) {
    const float* w   = (const float*)d_in[0];
    const int*   idx = (const int*)  d_in[1];
    const float* bb  = (const float*)d_in[2];

    const int smem_bytes = (2 * KCHUNK * LDTA + KCHUNK * LDTB) * (int)sizeof(__half); // 134400
    cudaFuncSetAttribute(fused_kernel, cudaFuncAttributeMaxDynamicSharedMemorySize, smem_bytes);

    fused_kernel<<<dim3(4, 2, SPLITK), 256, smem_bytes>>>(w, idx, bb);
    reduce_kernel<<<128, 256>>>((float*)d_out);
}

// round 12
// speedup vs baseline: 1.1575x; 1.0175x over previous
#include <cuda_runtime.h>
#include <cuda_fp16.h>
#include <cstdint>

// ---------------------------------------------------------------------------
// out = sum_p w_p * kron8(blocks[idx[p]])  -> 256x256
// G[a,b] = sum_p (w_p A_p[a]) B_p[b];  out[(iH16+iL),(jH16+jL)] = G[iH16+jH, iL16+jL]
// A = w*ternary -> split w = w_hi + w_lo (fp16): A_hi, A_lo, B exact fp16.
// G = A_hi^T B + A_lo^T B via mma.sync f16->f32, tiles generated in smem.
// R12: SPLITK=16/KCHUNK=256 (no padding); fused kernel 512 threads (16 warps,
//      16x32 warp tiles); reduce = 4 thr/output x 4 loads + shfl quad-combine.
// ---------------------------------------------------------------------------

#define POP      4096
#define SPLITK   16
#define KCHUNK   256                 // 16*256 = 4096 exactly
#define KSTEPS   16                  // 256/16
#define LDTA     72                  // A tile row stride (halfs), 64 + pad
#define LDTB     136                 // B tile row stride (halfs), 128 + pad

__device__ float g_part[SPLITK * 256 * 256];   // 4.2 MB split-K partials

// ---------------- warp-MMA helpers (sm_80+ PTX, valid at compute_103) ------
__device__ __forceinline__ unsigned smem_u32(const void* p) {
    unsigned a;
    asm("{ .reg .u64 t; cvta.to.shared.u64 t, %1; cvt.u32.u64 %0, t; }" : "=r"(a) : "l"(p));
    return a;
}
__device__ __forceinline__ void ldsm_x4_t(uint32_t* r, unsigned a) {
    asm volatile("ldmatrix.sync.aligned.m8n8.x4.trans.shared.b16 {%0,%1,%2,%3}, [%4];"
                 : "=r"(r[0]), "=r"(r[1]), "=r"(r[2]), "=r"(r[3]) : "r"(a));
}
__device__ __forceinline__ void ldsm_x2_t(uint32_t* r, unsigned a) {
    asm volatile("ldmatrix.sync.aligned.m8n8.x2.trans.shared.b16 {%0,%1}, [%2];"
                 : "=r"(r[0]), "=r"(r[1]) : "r"(a));
}
__device__ __forceinline__ void mma16816(float* d, const uint32_t* a, const uint32_t* b) {
    asm volatile("mma.sync.aligned.m16n8k16.row.col.f32.f16.f16.f32 "
                 "{%0,%1,%2,%3}, {%4,%5,%6,%7}, {%8,%9}, {%0,%1,%2,%3};"
                 : "+f"(d[0]), "+f"(d[1]), "+f"(d[2]), "+f"(d[3])
                 : "r"(a[0]), "r"(a[1]), "r"(a[2]), "r"(a[3]), "r"(b[0]), "r"(b[1]));
}

// ---------------------------------------------------------------------------
// Fused kernel: grid (4 mb, 2 nb, 16 z) = 128 CTAs, 512 threads (16 warps).
// A tile 64 a-cols (a bits [7:6] = mb), B tile 128 b-cols (b bit 7 = nb).
// Warp-tile 16 rows x 32 cols: wm = wid&3 (m-quarter), wn = wid>>2 (n-quarter).
// ---------------------------------------------------------------------------
__global__ void __launch_bounds__(512, 1) fused_kernel(
        const float* __restrict__ w,
        const int*   __restrict__ idxg,
        const float* __restrict__ bbg) {
    extern __shared__ __half smem[];
    __half* As = smem;                               // [KCHUNK][LDTA]
    __half* Al = smem + KCHUNK * LDTA;
    __half* Bs = smem + 2 * KCHUNK * LDTA;           // [KCHUNK][LDTB]
    __shared__ float bb[144];
    __shared__ int   sidx[KCHUNK * 8];
    __shared__ float sw[KCHUNK];
    __shared__ uint4 vt[4 * KCHUNK];                 // V-tables: 2 uint4/entry

    const int tid = threadIdx.x, lane = tid & 31, wid = tid >> 5;
    const int mb = blockIdx.x, nb = blockIdx.y, z = blockIdx.z;
    const int gbase = z * KCHUNK;

    // ---- Stage constants (no guards: 16*256 = 4096 exactly) ----
    if (tid < 144) bb[tid] = bbg[tid];
    #pragma unroll
    for (int i = tid; i < KCHUNK * 8; i += 512)
        sidx[i] = __ldg(&idxg[gbase * 8 + i]);
    if (tid < KCHUNK) sw[tid] = __ldg(&w[gbase + tid]);
    __syncthreads();

    // ---- Pre-pass: per-(genome, side) V-table (kron of codons 2,3 / 6,7) ----
    {
        const int i = tid;                   // 512 tasks, one per thread
        const int gl = i & (KCHUNK - 1);
        const int cb = (i < KCHUNK) ? 2 : 6;
        const int ia = sidx[gl * 8 + cb], ib = sidx[gl * 8 + cb + 1];
        __half2 Vh[8];
        #pragma unroll
        for (int p = 0; p < 2; p++)
          #pragma unroll
          for (int q = 0; q < 2; q++)
            #pragma unroll
            for (int r = 0; r < 2; r++) {
                const float va = bb[ia * 4 + p * 2 + r];
                Vh[((p*2+q)*4 + r*2) >> 1] =
                    __floats2half2_rn(va * bb[ib * 4 + q * 2],
                                      va * bb[ib * 4 + q * 2 + 1]);
            }
        uint4 u0, u1;
        u0.x = *(unsigned*)&Vh[0]; u0.y = *(unsigned*)&Vh[1];
        u0.z = *(unsigned*)&Vh[2]; u0.w = *(unsigned*)&Vh[3];
        u1.x = *(unsigned*)&Vh[4]; u1.y = *(unsigned*)&Vh[5];
        u1.z = *(unsigned*)&Vh[6]; u1.w = *(unsigned*)&Vh[7];
        vt[i * 2]     = u0;
        vt[i * 2 + 1] = u1;
    }
    __syncthreads();

    // ---- Build A hi/lo: tasks (gl, xi), xi 0..3; x = mb*4 + xi ----
    #pragma unroll
    for (int i = tid; i < KCHUNK * 4; i += 512) {
        const int gl = i >> 2, xi = i & 3;
        const float u = bb[sidx[gl*8+0] * 4 + (mb >> 1) * 2 + (xi >> 1)]
                      * bb[sidx[gl*8+1] * 4 + (mb & 1) * 2 + (xi & 1)];
        const float wf  = sw[gl];
        const float whf = __half2float(__float2half_rn(wf));
        const float wlf = __half2float(__float2half_rn(wf - whf));
        const __half2 ph = __float2half2_rn(whf * u);   // exact {0, +/-w_hi}
        const __half2 pl = __float2half2_rn(wlf * u);

        const uint4 v0 = vt[gl * 2], v1 = vt[gl * 2 + 1];
        const unsigned vv[8] = {v0.x, v0.y, v0.z, v0.w, v1.x, v1.y, v1.z, v1.w};
        #pragma unroll
        for (int qq = 0; qq < 4; qq++) {
            const __half2 a0 = *(const __half2*)&vv[2*qq];
            const __half2 a1 = *(const __half2*)&vv[2*qq+1];
            __half2 h0 = __hmul2(ph, a0), h1 = __hmul2(ph, a1);
            __half2 l0 = __hmul2(pl, a0), l1 = __hmul2(pl, a1);
            const int col = (qq << 4) | (xi << 2);
            uint2 uh; uh.x = *(unsigned*)&h0; uh.y = *(unsigned*)&h1;
            uint2 ul; ul.x = *(unsigned*)&l0; ul.y = *(unsigned*)&l1;
            *(uint2*)&As[gl * LDTA + col] = uh;
            *(uint2*)&Al[gl * LDTA + col] = ul;
        }
    }

    // ---- Build B: tasks (gl, xi), xi 0..7; x = nb*8 + xi ----
    #pragma unroll
    for (int i = tid; i < KCHUNK * 8; i += 512) {
        const int gl = i >> 3, xi = i & 7;
        const float u = bb[sidx[gl*8+4] * 4 + nb * 2 + ((xi >> 1) & 1)]
                      * bb[sidx[gl*8+5] * 4 + ((xi >> 2) & 1) * 2 + (xi & 1)];
        const __half2 uh2 = __float2half2_rn(u);

        const uint4 v0 = vt[(KCHUNK + gl) * 2], v1 = vt[(KCHUNK + gl) * 2 + 1];
        const unsigned vv[8] = {v0.x, v0.y, v0.z, v0.w, v1.x, v1.y, v1.z, v1.w};
        const int colbase = (((xi >> 2) & 1) << 6) | ((xi & 3) << 2);
        #pragma unroll
        for (int qq = 0; qq < 4; qq++) {
            const __half2 a0 = *(const __half2*)&vv[2*qq];
            const __half2 a1 = *(const __half2*)&vv[2*qq+1];
            __half2 h0 = __hmul2(uh2, a0), h1 = __hmul2(uh2, a1);
            const int col = colbase | (qq << 4);
            uint2 uv; uv.x = *(unsigned*)&h0; uv.y = *(unsigned*)&h1;
            *(uint2*)&Bs[gl * LDTB + col] = uv;
        }
    }
    __syncthreads();

    // ---- HMMA mainloop: 16 warps, 16x32 warp tiles ----
    const int wm = wid & 3;
    const int wn = wid >> 2;
    const int arow = (lane & 7) + ((lane >> 4) << 3);
    const int acol = wm * 16 + ((lane >> 3) & 1) * 8;
    const int bl = lane & 15;
    const int brow = (bl & 7) + ((bl >> 3) << 3);

    const unsigned aHi = smem_u32(&As[arow * LDTA + acol]);
    const unsigned aLo = smem_u32(&Al[arow * LDTA + acol]);
    const unsigned bBa = smem_u32(&Bs[brow * LDTB + wn * 32]);

    float acc[4][4];
    #pragma unroll
    for (int j = 0; j < 4; j++)
        #pragma unroll
        for (int q = 0; q < 4; q++) acc[j][q] = 0.f;

    #pragma unroll
    for (int ks = 0; ks < KSTEPS; ks++) {
        const unsigned koa = (unsigned)(ks * 16 * LDTA * 2);
        const unsigned kob = (unsigned)(ks * 16 * LDTB * 2);
        uint32_t bf[4][2];
        #pragma unroll
        for (int nt = 0; nt < 4; nt++) ldsm_x2_t(bf[nt], bBa + kob + nt * 16);
        uint32_t ah[4], al[4];
        ldsm_x4_t(ah, aHi + koa);
        ldsm_x4_t(al, aLo + koa);
        #pragma unroll
        for (int nt = 0; nt < 4; nt++) {
            mma16816(acc[nt], ah, bf[nt]);
            mma16816(acc[nt], al, bf[nt]);
        }
    }

    // ---- Epilogue: write 16x32 per warp into 64x128 split-K partial ----
    float* part = g_part + z * 65536;
    const int r0 = mb * 64 + wm * 16;
    const int c0 = nb * 128 + wn * 32;
    #pragma unroll
    for (int nt = 0; nt < 4; nt++) {
        const int a = r0 + (lane >> 2);
        const int b = c0 + nt * 8 + (lane & 3) * 2;
        *(float2*)&part[a * 256 + b]       = make_float2(acc[nt][0], acc[nt][1]);
        *(float2*)&part[(a + 8) * 256 + b] = make_float2(acc[nt][2], acc[nt][3]);
    }
}

// ---------------------------------------------------------------------------
// Reduce: 4 threads per output float4, 4 slices each (MLP=4), shfl quad
// combine, Kronecker-permuted store. grid 256 x 256 thr = 65K threads.
// ---------------------------------------------------------------------------
__global__ void __launch_bounds__(256) reduce_kernel(float* __restrict__ out) {
    const int t = threadIdx.x;
    const int o = blockIdx.x * 64 + (t >> 2);        // output float4 index
    const int q = t & 3;                             // k-quad
    const float4* src = (const float4*)g_part + o;

    float4 v[4];
    #pragma unroll
    for (int k = 0; k < 4; k++) v[k] = src[(size_t)(q * 4 + k) * 16384];

    float4 s = v[0];
    #pragma unroll
    for (int k = 1; k < 4; k++) {
        s.x += v[k].x; s.y += v[k].y; s.z += v[k].z; s.w += v[k].w;
    }
    #pragma unroll
    for (int m = 1; m <= 2; m <<= 1) {
        s.x += __shfl_xor_sync(0xffffffffu, s.x, m);
        s.y += __shfl_xor_sync(0xffffffffu, s.y, m);
        s.z += __shfl_xor_sync(0xffffffffu, s.z, m);
        s.w += __shfl_xor_sync(0xffffffffu, s.w, m);
    }
    if (q == 0) {
        const int tt = o * 4;
        const int a = tt >> 8, b = tt & 255;
        const int iH = a >> 4, jH = a & 15;
        const int iL = b >> 4, jL = b & 15;          // jL multiple of 4
        *(float4*)(out + (iH * 16 + iL) * 256 + jH * 16 + jL) = s;
    }
}

extern "C" void kernel_launch(void* const* d_in, const int* in_sizes, int n_in,
                              void* d_out, int out_size) {
    const float* w   = (const float*)d_in[0];
    const int*   idx = (const int*)  d_in[1];
    const float* bb  = (const float*)d_in[2];

    const int smem_bytes = (2 * KCHUNK * LDTA + KCHUNK * LDTB) * (int)sizeof(__half); // 143360
    cudaFuncSetAttribute(fused_kernel, cudaFuncAttributeMaxDynamicSharedMemorySize, smem_bytes);

    fused_kernel<<<dim3(4, 2, SPLITK), 512, smem_bytes>>>(w, idx, bb);
    reduce_kernel<<<256, 256>>>((float*)d_out);
}